// round 10
// baseline (speedup 1.0000x reference)
#include <cuda_runtime.h>
#include <cuda.h>
#include <cuda_bf16.h>
#include <math.h>
#include <stdint.h>

#if defined(__CUDA_ARCH__)
#if defined(__CUDA_ARCH_FEAT_SM103_ALL) || defined(__CUDA_ARCH_FEAT_SM100_ALL) || defined(__CUDA_ARCH_FEAT_SM101_ALL)
#define TCGEN05_OK 1
#else
#define TCGEN05_OK 0
#endif
#else
#define TCGEN05_OK 0
#endif

#define NBATCH  2
#define S_LEN   2048
#define D_MODEL 2048
#define DHEAD   128
#define M_ROWS  4096
#define DD      (D_MODEL * D_MODEL)
#define NSM     148
#define NITEMS  512
#define LOG2E   1.4426950408889634f

// ---------------- scratch ----------------
__device__ __nv_bfloat16 g_xhi[(size_t)M_ROWS * D_MODEL];
__device__ __nv_bfloat16 g_xlo[(size_t)M_ROWS * D_MODEL];
__device__ __nv_bfloat16 g_yhi[(size_t)M_ROWS * D_MODEL];
__device__ __nv_bfloat16 g_ylo[(size_t)M_ROWS * D_MODEL];
__device__ __nv_bfloat16 g_whi[(size_t)4 * DD];
__device__ __nv_bfloat16 g_wlo[(size_t)4 * DD];
__device__ __nv_bfloat16 g_qhi[(size_t)M_ROWS * D_MODEL];
__device__ __nv_bfloat16 g_qlo[(size_t)M_ROWS * D_MODEL];
__device__ __nv_bfloat16 g_khi[(size_t)M_ROWS * D_MODEL];
__device__ __nv_bfloat16 g_klo[(size_t)M_ROWS * D_MODEL];
__device__ __nv_bfloat16 g_vthi[(size_t)M_ROWS * D_MODEL];  // [b*2048+d][s]
__device__ __nv_bfloat16 g_vtlo[(size_t)M_ROWS * D_MODEL];

// ---------------- PTX helpers ----------------
__device__ __forceinline__ uint32_t smem_u32(const void* p) {
    uint32_t a;
    asm("{ .reg .u64 t; cvta.to.shared.u64 t, %1; cvt.u32.u64 %0, t; }"
        : "=r"(a) : "l"(p));
    return a;
}
__device__ __forceinline__ uint32_t elect1() {
#if TCGEN05_OK
    uint32_t p;
    asm volatile(
        "{\n\t.reg .pred p;\n\t"
        "elect.sync _|p, 0xFFFFFFFF;\n\t"
        "selp.b32 %0, 1, 0, p;\n\t}"
        : "=r"(p));
    return p;
#else
    return 0;
#endif
}
__device__ __forceinline__ void mbar_init(uint32_t addr, uint32_t count) {
    asm volatile("mbarrier.init.shared.b64 [%0], %1;" :: "r"(addr), "r"(count) : "memory");
}
__device__ __forceinline__ void mbar_inval(uint32_t addr) {
    asm volatile("mbarrier.inval.shared.b64 [%0];" :: "r"(addr) : "memory");
}
__device__ __forceinline__ void mbar_wait(uint32_t addr, uint32_t parity) {
    asm volatile(
        "{\n\t.reg .pred P;\n\t"
        "WL_%=:\n\t"
        "mbarrier.try_wait.parity.acquire.cta.shared::cta.b64 P, [%0], %1, 0x989680;\n\t"
        "@P bra.uni WD_%=;\n\t"
        "bra.uni WL_%=;\n\t"
        "WD_%=:\n\t}"
        :: "r"(addr), "r"(parity) : "memory");
}
__device__ __forceinline__ void mbar_expect(uint32_t mbar, uint32_t bytes) {
    asm volatile("mbarrier.arrive.expect_tx.shared.b64 _, [%0], %1;"
                 :: "r"(mbar), "r"(bytes) : "memory");
}
__device__ __forceinline__ void tma2d(uint32_t dst, const CUtensorMap* m,
                                      int x, int y, uint32_t mbar) {
    asm volatile(
        "cp.async.bulk.tensor.2d.shared::cta.global.tile.mbarrier::complete_tx::bytes "
        "[%0], [%1, {%2, %3}], [%4];"
        :: "r"(dst), "l"(m), "r"(x), "r"(y), "r"(mbar) : "memory");
}
__device__ __forceinline__ void tmem_alloc(uint32_t smem_dst, uint32_t ncols) {
#if TCGEN05_OK
    asm volatile("tcgen05.alloc.cta_group::1.sync.aligned.shared::cta.b32 [%0], %1;"
                 :: "r"(smem_dst), "r"(ncols) : "memory");
#endif
}
__device__ __forceinline__ void tmem_dealloc(uint32_t tmem, uint32_t ncols) {
#if TCGEN05_OK
    asm volatile("tcgen05.dealloc.cta_group::1.sync.aligned.b32 %0, %1;"
                 :: "r"(tmem), "r"(ncols));
#endif
}
__device__ __forceinline__ void tmem_relinquish() {
#if TCGEN05_OK
    asm volatile("tcgen05.relinquish_alloc_permit.cta_group::1.sync.aligned;");
#endif
}
__device__ __forceinline__ void mma_f16_ss(uint32_t d_tmem, uint64_t a_desc,
                                           uint64_t b_desc, uint32_t idesc,
                                           uint32_t enable_d) {
#if TCGEN05_OK
    asm volatile(
        "{\n\t.reg .pred p;\n\t"
        "setp.ne.u32 p, %4, 0;\n\t"
        "tcgen05.mma.cta_group::1.kind::f16 [%0], %1, %2, %3, {%5, %5, %5, %5}, p;\n\t}"
        :: "r"(d_tmem), "l"(a_desc), "l"(b_desc), "r"(idesc), "r"(enable_d), "r"(0u)
        : "memory");
#endif
}
__device__ __forceinline__ void mma_commit(uint32_t mbar_addr) {
#if TCGEN05_OK
    asm volatile(
        "tcgen05.commit.cta_group::1.mbarrier::arrive::one.shared::cluster.b64 [%0];"
        :: "r"(mbar_addr) : "memory");
#endif
}
__device__ __forceinline__ void tcg_fence_after() {
#if TCGEN05_OK
    asm volatile("tcgen05.fence::after_thread_sync;" ::: "memory");
#endif
}
__device__ __forceinline__ void fence_proxy_async_s() {
    asm volatile("fence.proxy.async.shared::cta;" ::: "memory");
}
__device__ __forceinline__ void tcg_wait_ld() {
#if TCGEN05_OK
    asm volatile("tcgen05.wait::ld.sync.aligned;" ::: "memory");
#endif
}
__device__ __forceinline__ void ldtm_x32(uint32_t* r, uint32_t addr) {
#if TCGEN05_OK
    asm volatile(
        "tcgen05.ld.sync.aligned.32x32b.x32.b32 "
        "{%0, %1, %2, %3, %4, %5, %6, %7, "
        " %8, %9, %10, %11, %12, %13, %14, %15, "
        " %16, %17, %18, %19, %20, %21, %22, %23, "
        " %24, %25, %26, %27, %28, %29, %30, %31}, [%32];"
        : "=r"(r[0]),  "=r"(r[1]),  "=r"(r[2]),  "=r"(r[3]),
          "=r"(r[4]),  "=r"(r[5]),  "=r"(r[6]),  "=r"(r[7]),
          "=r"(r[8]),  "=r"(r[9]),  "=r"(r[10]), "=r"(r[11]),
          "=r"(r[12]), "=r"(r[13]), "=r"(r[14]), "=r"(r[15]),
          "=r"(r[16]), "=r"(r[17]), "=r"(r[18]), "=r"(r[19]),
          "=r"(r[20]), "=r"(r[21]), "=r"(r[22]), "=r"(r[23]),
          "=r"(r[24]), "=r"(r[25]), "=r"(r[26]), "=r"(r[27]),
          "=r"(r[28]), "=r"(r[29]), "=r"(r[30]), "=r"(r[31])
        : "r"(addr));
#else
    for (int i = 0; i < 32; i++) r[i] = 0;
#endif
}

#define DESC_BASE ((2ull << 61) | (1ull << 46) | (64ull << 32) | (1ull << 16))
#define IDESC_N256 ((1u << 4) | (1u << 7) | (1u << 10) | (32u << 17) | (8u << 24))
#define IDESC_N128 ((1u << 4) | (1u << 7) | (1u << 10) | (16u << 17) | (8u << 24))
#define IDESC_N64  ((1u << 4) | (1u << 7) | (1u << 10) | (8u << 17)  | (8u << 24))

__device__ __forceinline__ uint32_t sw128(uint32_t bo) {
    return bo ^ ((bo >> 3) & 0x70);
}
__device__ __forceinline__ uint32_t pack_bf2(float a, float b) {
    __nv_bfloat162 v;
    v.x = __float2bfloat16(a);
    v.y = __float2bfloat16(b);
    return *(uint32_t*)&v;
}
__device__ __forceinline__ float ex2f(float x) {
    float y;
    asm("ex2.approx.ftz.f32 %0, %1;" : "=f"(y) : "f"(x));
    return y;
}

// ---------------- fp32 -> (hi, lo) bf16 split ----------------
__device__ __forceinline__ void split_body(const float* src, __nv_bfloat16* hi,
                                           __nv_bfloat16* lo, int i) {
    float4 v = ((const float4*)src)[i];
    __nv_bfloat16 h0 = __float2bfloat16(v.x);
    __nv_bfloat16 h1 = __float2bfloat16(v.y);
    __nv_bfloat16 h2 = __float2bfloat16(v.z);
    __nv_bfloat16 h3 = __float2bfloat16(v.w);
    uint2 hh, ll;
    hh.x = pack_bf2(v.x, v.y); hh.y = pack_bf2(v.z, v.w);
    ll.x = pack_bf2(v.x - __bfloat162float(h0), v.y - __bfloat162float(h1));
    ll.y = pack_bf2(v.z - __bfloat162float(h2), v.w - __bfloat162float(h3));
    *(uint2*)(hi + 4 * (size_t)i) = hh;
    *(uint2*)(lo + 4 * (size_t)i) = ll;
}

__global__ __launch_bounds__(256) void split_bf16_kernel(
    const float* __restrict__ src,
    __nv_bfloat16* __restrict__ hi, __nv_bfloat16* __restrict__ lo, int n4)
{
    int i = blockIdx.x * 256 + threadIdx.x;
    if (i < n4) split_body(src, hi, lo, i);
}

__global__ __launch_bounds__(256) void wsplit4_kernel(
    const float* __restrict__ s0, const float* __restrict__ s1,
    const float* __restrict__ s2, const float* __restrict__ s3,
    __nv_bfloat16* __restrict__ hi, __nv_bfloat16* __restrict__ lo, int n4)
{
    int i = blockIdx.x * 256 + threadIdx.x;
    if (i >= n4) return;
    int k = blockIdx.y;
    const float* src = (k == 0) ? s0 : (k == 1) ? s1 : (k == 2) ? s2 : s3;
    split_body(src, hi + (size_t)k * DD, lo + (size_t)k * DD, i);
}

// ---------------- 128x256 combined-term GEMM ----------------
#define GST_A_HI 0
#define GST_A_LO 16384
#define GST_B_HI 32768
#define GST_B_LO 65536
#define GST_SIZE 98304
#define G_OFF(s) (1024 + (s) * GST_SIZE)
#define GSMEM_TOTAL (1024 + 2 * GST_SIZE)

#if TCGEN05_OK
__device__ __forceinline__ void gemm256_mainloop(
    char* smem, uint32_t sb, uint32_t tmem, int tid, int wid,
    const __nv_bfloat16* Ahi, const __nv_bfloat16* Alo,
    const __nv_bfloat16* Bhi, const __nv_bfloat16* Blo,
    int bm, int bn, int K)
{
    uint32_t ph0 = 0, ph1 = 0;
    for (int i = 0; i < 32; i++) {
        const int k0 = i * 64;
        const int buf = i & 1;
        if (i >= 2) {
            if (buf == 0) { mbar_wait(sb + 8, ph0);  ph0 ^= 1; }
            else          { mbar_wait(sb + 16, ph1); ph1 ^= 1; }
        }
        const uint32_t off = G_OFF(buf);
#pragma unroll
        for (int j = 0; j < 4; j++) {
            int u = tid + j * 256;
            int r = u >> 3, cs = u & 7;
            uint32_t sw = sw128((uint32_t)u * 16u);
            size_t g = (size_t)(bm + r) * K + k0 + cs * 8;
            *(uint4*)(smem + off + GST_A_HI + sw) = *(const uint4*)(Ahi + g);
            *(uint4*)(smem + off + GST_A_LO + sw) = *(const uint4*)(Alo + g);
        }
#pragma unroll
        for (int j = 0; j < 8; j++) {
            int u = tid + j * 256;
            int r = u >> 3, cs = u & 7;
            uint32_t sw = sw128((uint32_t)u * 16u);
            size_t g = (size_t)(bn + r) * K + k0 + cs * 8;
            *(uint4*)(smem + off + GST_B_HI + sw) = *(const uint4*)(Bhi + g);
            *(uint4*)(smem + off + GST_B_LO + sw) = *(const uint4*)(Blo + g);
        }
        __syncthreads();
        if (wid == 0 && elect1()) {
            fence_proxy_async_s();
            uint64_t dAh = DESC_BASE | ((uint64_t)((sb + off + GST_A_HI) >> 4) & 0x3FFF);
            uint64_t dAl = DESC_BASE | ((uint64_t)((sb + off + GST_A_LO) >> 4) & 0x3FFF);
            uint64_t dBh = DESC_BASE | ((uint64_t)((sb + off + GST_B_HI) >> 4) & 0x3FFF);
            uint64_t dBl = DESC_BASE | ((uint64_t)((sb + off + GST_B_LO) >> 4) & 0x3FFF);
#pragma unroll
            for (int k = 0; k < 4; k++)
                mma_f16_ss(tmem, dAh + k * 2, dBh + k * 2, IDESC_N256, !(i == 0 && k == 0));
#pragma unroll
            for (int k = 0; k < 4; k++)
                mma_f16_ss(tmem, dAh + k * 2, dBl + k * 2, IDESC_N256, 1u);
#pragma unroll
            for (int k = 0; k < 4; k++)
                mma_f16_ss(tmem, dAl + k * 2, dBh + k * 2, IDESC_N256, 1u);
            mma_commit(buf ? (sb + 16) : (sb + 8));
        }
    }
    mbar_wait(sb + 16, ph1);
    tcg_fence_after();
    __syncthreads();
}
#endif

// out-projection: fp32 epilogue
__global__ __launch_bounds__(256) void gemm_out_kernel(
    const __nv_bfloat16* __restrict__ Ahi, const __nv_bfloat16* __restrict__ Alo,
    const __nv_bfloat16* __restrict__ Bhi, const __nv_bfloat16* __restrict__ Blo,
    float* __restrict__ C, int K, int N)
{
#if TCGEN05_OK
    extern __shared__ char smem[];
    const uint32_t sb = smem_u32(smem);
    const int tid = threadIdx.x;
    const int wid = tid >> 5;
    const int lid = tid & 31;
    const int bm = blockIdx.y * 128;
    const int bn = blockIdx.x * 256;

    if (wid == 0) { tmem_alloc(sb, 256); tmem_relinquish(); }
    if (tid == 0) { mbar_init(sb + 8, 1); mbar_init(sb + 16, 1); }
    __syncthreads();
    uint32_t tmem;
    asm volatile("ld.shared.b32 %0, [%1];" : "=r"(tmem) : "r"(sb));

    gemm256_mainloop(smem, sb, tmem, tid, wid, Ahi, Alo, Bhi, Blo, bm, bn, K);

    float* st = (float*)(smem + 1024);
#pragma unroll
    for (int hb = 0; hb < 4; hb++) {
        if (wid < 4) {
            uint32_t d0[32], d1[32];
            ldtm_x32(d0, tmem + hb * 64);
            ldtm_x32(d1, tmem + hb * 64 + 32);
            tcg_wait_ld();
            float* srow = st + (wid * 32 + lid) * 68;
#pragma unroll
            for (int c = 0; c < 32; c++) {
                srow[c]      = __uint_as_float(d0[c]);
                srow[32 + c] = __uint_as_float(d1[c]);
            }
        }
        __syncthreads();
#pragma unroll
        for (int j = 0; j < 8; j++) {
            int u = tid + j * 256;
            int row = u >> 4, c4 = u & 15;
            float4 v = *(const float4*)(st + row * 68 + c4 * 4);
            *(float4*)(C + (size_t)(bm + row) * N + bn + hb * 64 + c4 * 4) = v;
        }
        __syncthreads();
    }
    if (tid == 0) { mbar_inval(sb + 8); mbar_inval(sb + 16); }
    if (wid == 0) tmem_dealloc(tmem, 256);
#endif
}

// fused QKV: rgn 0=Q(hi/lo, scaled), 1=K(hi/lo), 2=V -> TRANSPOSED hi/lo
__global__ __launch_bounds__(256) void gemm_qkv_kernel(
    const __nv_bfloat16* __restrict__ Ahi, const __nv_bfloat16* __restrict__ Alo,
    const __nv_bfloat16* __restrict__ Whi, const __nv_bfloat16* __restrict__ Wlo,
    __nv_bfloat16* __restrict__ Qh, __nv_bfloat16* __restrict__ Ql,
    __nv_bfloat16* __restrict__ Kh, __nv_bfloat16* __restrict__ Kl,
    __nv_bfloat16* __restrict__ VTh, __nv_bfloat16* __restrict__ VTl,
    float qscale)
{
#if TCGEN05_OK
    extern __shared__ char smem[];
    const uint32_t sb = smem_u32(smem);
    const int tid = threadIdx.x;
    const int wid = tid >> 5;
    const int lid = tid & 31;
    const int rgn = blockIdx.x >> 3;
    const int bn  = (blockIdx.x & 7) * 256;
    const int bm  = blockIdx.y * 128;
    const int N   = D_MODEL, K = D_MODEL;

    if (wid == 0) { tmem_alloc(sb, 256); tmem_relinquish(); }
    if (tid == 0) { mbar_init(sb + 8, 1); mbar_init(sb + 16, 1); }
    __syncthreads();
    uint32_t tmem;
    asm volatile("ld.shared.b32 %0, [%1];" : "=r"(tmem) : "r"(sb));

    gemm256_mainloop(smem, sb, tmem, tid, wid, Ahi, Alo,
                     Whi + (size_t)rgn * DD, Wlo + (size_t)rgn * DD, bm, bn, K);

    const float scale = (rgn == 0) ? qscale : 1.0f;
    float* st = (float*)(smem + 1024);
    const int bQ = bm >> 11;           // batch index (V transpose)
    const int sBase = bm & 2047;       // seq offset within batch
#pragma unroll
    for (int hb = 0; hb < 4; hb++) {
        if (wid < 4) {
            uint32_t d0[32], d1[32];
            ldtm_x32(d0, tmem + hb * 64);
            ldtm_x32(d1, tmem + hb * 64 + 32);
            tcg_wait_ld();
            float* srow = st + (wid * 32 + lid) * 68;
#pragma unroll
            for (int c = 0; c < 32; c++) {
                srow[c]      = __uint_as_float(d0[c]);
                srow[32 + c] = __uint_as_float(d1[c]);
            }
        }
        __syncthreads();
        if (rgn == 2) {
            // transposed V write: vt[(bQ*2048 + d)][sBase + row]
#pragma unroll
            for (int j = 0; j < 32; j++) {
                int u = tid + j * 256;          // 8192 = 128 rows x 64 cols
                int row = u & 127, c = u >> 7;
                float v = st[row * 68 + c];
                __nv_bfloat16 h = __float2bfloat16(v);
                __nv_bfloat16 l = __float2bfloat16(v - __bfloat162float(h));
                size_t d = (size_t)(bn + hb * 64 + c);
                size_t addr = ((size_t)bQ * D_MODEL + d) * S_LEN + sBase + row;
                VTh[addr] = h;
                VTl[addr] = l;
            }
        } else {
#pragma unroll
            for (int j = 0; j < 8; j++) {
                int u = tid + j * 256;
                int row = u >> 4, c4 = u & 15;
                float4 v = *(const float4*)(st + row * 68 + c4 * 4);
                size_t grow = (size_t)(bm + row);
                int gcol = bn + hb * 64 + c4 * 4;
                float v0 = v.x * scale, v1 = v.y * scale;
                float v2 = v.z * scale, v3 = v.w * scale;
                __nv_bfloat16 h0 = __float2bfloat16(v0);
                __nv_bfloat16 h1 = __float2bfloat16(v1);
                __nv_bfloat16 h2 = __float2bfloat16(v2);
                __nv_bfloat16 h3 = __float2bfloat16(v3);
                uint2 hh, ll;
                hh.x = pack_bf2(v0, v1); hh.y = pack_bf2(v2, v3);
                ll.x = pack_bf2(v0 - __bfloat162float(h0), v1 - __bfloat162float(h1));
                ll.y = pack_bf2(v2 - __bfloat162float(h2), v3 - __bfloat162float(h3));
                __nv_bfloat16* H = (rgn == 0) ? Qh : Kh;
                __nv_bfloat16* L = (rgn == 0) ? Ql : Kl;
                *(uint2*)(H + grow * N + gcol) = hh;
                *(uint2*)(L + grow * N + gcol) = ll;
            }
        }
        __syncthreads();
    }
    if (tid == 0) { mbar_inval(sb + 8); mbar_inval(sb + 16); }
    if (wid == 0) tmem_dealloc(tmem, 256);
#endif
}

// ---------------- persistent attention: max-free softmax, TMEM O-accum ------
#define AT_RED    1024
#define AT_QHI    3072
#define AT_QLO    35840
#define AT_KV0    68608
#define AT_KV1    134144
#define AT_PHI    199680
#define AT_PLO    216064
#define AT_TOTAL  232448
#define AT_STAGE  AT_KV0

#if TCGEN05_OK
__device__ __forceinline__ void fill_kv_tma(
    uint32_t sb, uint32_t kvb,
    const CUtensorMap* mKh, const CUtensorMap* mKl,
    const CUtensorMap* mVh, const CUtensorMap* mVl,
    int b, int bh, int h, int jt, uint32_t mbar)
{
    const int kx = h * 128, ky = b * S_LEN + jt * 64;
    tma2d(sb + kvb,         mKh, kx,      ky, mbar);
    tma2d(sb + kvb + 8192,  mKh, kx + 64, ky, mbar);
    tma2d(sb + kvb + 16384, mKl, kx,      ky, mbar);
    tma2d(sb + kvb + 24576, mKl, kx + 64, ky, mbar);
    tma2d(sb + kvb + 32768, mVh, jt * 64, bh * 128, mbar);
    tma2d(sb + kvb + 49152, mVl, jt * 64, bh * 128, mbar);
}
__device__ __forceinline__ void issue_qk(uint32_t sb, uint32_t S_T, uint32_t kvb) {
    uint64_t dQh = DESC_BASE | ((uint64_t)((sb + AT_QHI) >> 4) & 0x3FFF);
    uint64_t dQl = DESC_BASE | ((uint64_t)((sb + AT_QLO) >> 4) & 0x3FFF);
    uint64_t dKh = DESC_BASE | ((uint64_t)((sb + kvb) >> 4) & 0x3FFF);
    uint64_t dKl = DESC_BASE | ((uint64_t)((sb + kvb + 16384) >> 4) & 0x3FFF);
    const uint64_t qo[8] = {0, 2, 4, 6, 1024, 1026, 1028, 1030};
    const uint64_t ko[8] = {0, 2, 4, 6, 512, 514, 516, 518};
    uint64_t aT[3] = {dQh, dQh, dQl};
    uint64_t bT[3] = {dKh, dKl, dKh};
#pragma unroll
    for (int t = 0; t < 3; t++)
#pragma unroll
        for (int s = 0; s < 8; s++)
            mma_f16_ss(S_T, aT[t] + qo[s], bT[t] + ko[s], IDESC_N64, !(t == 0 && s == 0));
    mma_commit(sb + 8);
}
// PV accumulates into persistent O; first=1 zero-initializes (enable_d=0 on 1st MMA)
__device__ __forceinline__ void issue_pv(uint32_t sb, uint32_t O_T, uint32_t kvb,
                                         int first, int do_commit) {
    uint64_t dPh = DESC_BASE | ((uint64_t)((sb + AT_PHI) >> 4) & 0x3FFF);
    uint64_t dPl = DESC_BASE | ((uint64_t)((sb + AT_PLO) >> 4) & 0x3FFF);
    uint64_t dVh = DESC_BASE | ((uint64_t)((sb + kvb + 32768) >> 4) & 0x3FFF);
    uint64_t dVl = DESC_BASE | ((uint64_t)((sb + kvb + 49152) >> 4) & 0x3FFF);
    uint64_t aT[3] = {dPh, dPh, dPl};
    uint64_t bT[3] = {dVh, dVl, dVh};
#pragma unroll
    for (int t = 0; t < 3; t++)
#pragma unroll
        for (int s = 0; s < 4; s++)
            mma_f16_ss(O_T, aT[t] + 2 * s, bT[t] + 2 * s, IDESC_N128,
                       !(first && t == 0 && s == 0));
    if (do_commit) mma_commit(sb + 16);
}
#endif

__global__ __launch_bounds__(256) void attn_tc_kernel(
    const __grid_constant__ CUtensorMap mQh, const __grid_constant__ CUtensorMap mQl,
    const __grid_constant__ CUtensorMap mKh, const __grid_constant__ CUtensorMap mKl,
    const __grid_constant__ CUtensorMap mVh, const __grid_constant__ CUtensorMap mVl,
    __nv_bfloat16* __restrict__ Yhi, __nv_bfloat16* __restrict__ Ylo)
{
#if TCGEN05_OK
    extern __shared__ char smem[];
    const uint32_t sb = smem_u32(smem);
    const int tid = threadIdx.x;
    const int w   = tid >> 5;
    const int l   = tid & 31;
    const int r   = (w & 3) * 32 + l;
    const int hf  = w >> 2;
    const uint32_t woff = (uint32_t)(w & 3) << 21;

    if (w == 0) { tmem_alloc(sb, 512); tmem_relinquish(); }
    if (tid == 0) {
        mbar_init(sb + 8, 1);    // S (QK commits)
        mbar_init(sb + 16, 1);   // O (final PV commit per item)
        mbar_init(sb + 24, 1);   // kv_full[0]
        mbar_init(sb + 32, 1);   // kv_full[1]
    }
    __syncthreads();
    uint32_t tmem;
    asm volatile("ld.shared.b32 %0, [%1];" : "=r"(tmem) : "r"(sb));
    const uint32_t S_T0 = tmem;          // cols 0..63
    const uint32_t S_T1 = tmem + 64;     // cols 64..127
    const uint32_t O_T  = tmem + 128;    // cols 128..255 (persistent accum)

    uint32_t phS = 0, phO = 0, phK0 = 0, phK1 = 0;

    for (int rnd = 0; rnd < 4; rnd++) {
        int s = rnd * NSM + ((rnd & 1) ? (NSM - 1 - (int)blockIdx.x) : (int)blockIdx.x);
        if (s >= NITEMS) continue;
        const int qt = 15 - (s >> 5);     // serpentine LPT
        const int bh = s & 31;
        const int b  = bh >> 4;
        const int h  = bh & 15;
        const int njt = 2 * qt + 2;
        const int qg = qt * 128 + r;

        // ---- prologue: Q + KV(0) via TMA, then QK(0) ----
        if (tid == 0) {
            mbar_expect(sb + 24, 131072u);
            const int qx = h * 128, qy = b * S_LEN + qt * 128;
            tma2d(sb + AT_QHI,         &mQh, qx,      qy, sb + 24);
            tma2d(sb + AT_QHI + 16384, &mQh, qx + 64, qy, sb + 24);
            tma2d(sb + AT_QLO,         &mQl, qx,      qy, sb + 24);
            tma2d(sb + AT_QLO + 16384, &mQl, qx + 64, qy, sb + 24);
            fill_kv_tma(sb, AT_KV0, &mKh, &mKl, &mVh, &mVl, b, bh, h, 0, sb + 24);
            mbar_wait(sb + 24, phK0); phK0 ^= 1;
            issue_qk(sb, S_T0, AT_KV0);
        }

        float l_run = 0.0f;

        for (int jt = 0; jt < njt; jt++) {
            const uint32_t kvb  = (jt & 1) ? AT_KV1 : AT_KV0;
            const uint32_t kvbn = (jt & 1) ? AT_KV0 : AT_KV1;
            const uint32_t S_cur = (jt & 1) ? S_T1 : S_T0;

            // S(jt) ready; since PV(jt-1) was issued BEFORE QK(jt), this also
            // implies PV(jt-1) complete -> KV buffer kvbn and P buffer are free.
            mbar_wait(sb + 8, phS); phS ^= 1;
            tcg_fence_after();

            // prefetch KV(jt+1) into the freed buffer
            if (tid == 0 && jt + 1 < njt) {
                uint32_t kf = sb + 24 + 8 * ((jt + 1) & 1);
                mbar_expect(kf, 65536u);
                fill_kv_tma(sb, kvbn, &mKh, &mKl, &mVh, &mVl, b, bh, h, jt + 1, kf);
            }

            // ---- read S, max-free softmax (scores pre-scaled by log2e) ----
            uint32_t sr_[32];
            ldtm_x32(sr_, S_cur + hf * 32 + woff);
            tcg_wait_ld();
            const int kgb = jt * 64 + hf * 32;
            float p[32], psum = 0.0f;
#pragma unroll
            for (int i = 0; i < 32; i++) {
                float x = __uint_as_float(sr_[i]);
                p[i] = (kgb + i > qg) ? 0.0f : ex2f(x);
                psum += p[i];
            }
            l_run += psum;

            // ---- P -> bf16 hi/lo into smem ----
            {
                uint32_t rowbase = (uint32_t)(r >> 3) * 1024u + (uint32_t)(r & 7) * 128u;
#pragma unroll
                for (int i = 0; i < 32; i += 2) {
                    float p0 = p[i], p1 = p[i + 1];
                    __nv_bfloat16 h0 = __float2bfloat16(p0);
                    __nv_bfloat16 h1 = __float2bfloat16(p1);
                    uint32_t hp = pack_bf2(p0, p1);
                    uint32_t lp = pack_bf2(p0 - __bfloat162float(h0),
                                           p1 - __bfloat162float(h1));
                    uint32_t sw = sw128(rowbase + (uint32_t)(hf * 32 + i) * 2u);
                    *(uint32_t*)(smem + AT_PHI + sw) = hp;
                    *(uint32_t*)(smem + AT_PLO + sw) = lp;
                }
            }
            __syncthreads();   // P visible; all warps consumed S

            // ---- issue PV(jt) then QK(jt+1): order matters (see S-wait above)
            if (tid == 0) {
                fence_proxy_async_s();
                issue_pv(sb, O_T, kvb, jt == 0, jt == njt - 1);
                if (jt + 1 < njt) {
                    uint32_t kf = sb + 24 + 8 * ((jt + 1) & 1);
                    if ((jt + 1) & 1) { mbar_wait(kf, phK1); phK1 ^= 1; }
                    else              { mbar_wait(kf, phK0); phK0 ^= 1; }
                    issue_qk(sb, (jt & 1) ? S_T0 : S_T1, kvbn);
                }
            }
        }

        // ---- item epilogue: O is fully accumulated in TMEM ----
        mbar_wait(sb + 16, phO); phO ^= 1;
        tcg_fence_after();
        float O[64];
        {
            uint32_t o0[32], o1[32];
            ldtm_x32(o0, O_T + hf * 64 + woff);
            ldtm_x32(o1, O_T + hf * 64 + 32 + woff);
            tcg_wait_ld();
#pragma unroll
            for (int j = 0; j < 32; j++) {
                O[j]      = __uint_as_float(o0[j]);
                O[32 + j] = __uint_as_float(o1[j]);
            }
        }

        // reduce l across halves, normalize, stage, write
        __syncthreads();
        {
            float* red1 = (float*)(smem + AT_RED);
            red1[hf * 128 + r] = l_run;
        }
        __syncthreads();
        {
            const float* red1 = (const float*)(smem + AT_RED);
            float inv = 1.0f / (red1[r] + red1[128 + r]);
            float* st = (float*)(smem + AT_STAGE);
#pragma unroll
            for (int j = 0; j < 64; j += 4) {
                float4 v = make_float4(O[j] * inv, O[j + 1] * inv,
                                       O[j + 2] * inv, O[j + 3] * inv);
                *(float4*)(st + r * 132 + hf * 64 + j) = v;
            }
        }
        __syncthreads();
        {
            const float* st = (const float*)(smem + AT_STAGE);
#pragma unroll
            for (int j = 0; j < 16; j++) {
                int u = tid + j * 256;
                int row = u >> 5, c4 = u & 31;
                float4 v = *(const float4*)(st + row * 132 + c4 * 4);
                size_t g = ((size_t)(b * S_LEN + qt * 128 + row)) * D_MODEL + h * DHEAD + c4 * 4;
                __nv_bfloat16 h0 = __float2bfloat16(v.x);
                __nv_bfloat16 h1 = __float2bfloat16(v.y);
                __nv_bfloat16 h2 = __float2bfloat16(v.z);
                __nv_bfloat16 h3 = __float2bfloat16(v.w);
                uint2 hh, ll;
                hh.x = pack_bf2(v.x, v.y); hh.y = pack_bf2(v.z, v.w);
                ll.x = pack_bf2(v.x - __bfloat162float(h0), v.y - __bfloat162float(h1));
                ll.y = pack_bf2(v.z - __bfloat162float(h2), v.w - __bfloat162float(h3));
                *(uint2*)(Yhi + g) = hh;
                *(uint2*)(Ylo + g) = ll;
            }
        }
        __syncthreads();   // staging consumed before next item's TMA
    }

    if (tid == 0) {
        mbar_inval(sb + 8);  mbar_inval(sb + 16);
        mbar_inval(sb + 24); mbar_inval(sb + 32);
    }
    if (w == 0) tmem_dealloc(tmem, 512);
#endif
}

// ---------------- host ----------------
typedef CUresult (CUDAAPI *PFN_tmap)(
    CUtensorMap*, CUtensorMapDataType, cuuint32_t, void*,
    const cuuint64_t*, const cuuint64_t*, const cuuint32_t*, const cuuint32_t*,
    CUtensorMapInterleave, CUtensorMapSwizzle, CUtensorMapL2promotion,
    CUtensorMapFloatOOBfill);

static void mk2d(PFN_tmap enc, CUtensorMap* m, void* ptr, uint32_t b0, uint32_t b1)
{
    cuuint64_t dims[2] = {D_MODEL, M_ROWS};
    cuuint64_t strides[1] = {D_MODEL * 2};
    cuuint32_t box[2] = {b0, b1};
    cuuint32_t es[2] = {1, 1};
    enc(m, CU_TENSOR_MAP_DATA_TYPE_BFLOAT16, 2, ptr, dims, strides, box, es,
        CU_TENSOR_MAP_INTERLEAVE_NONE, CU_TENSOR_MAP_SWIZZLE_128B,
        CU_TENSOR_MAP_L2_PROMOTION_L2_128B, CU_TENSOR_MAP_FLOAT_OOB_FILL_NONE);
}

extern "C" void kernel_launch(void* const* d_in, const int* in_sizes, int n_in,
                              void* d_out, int out_size)
{
    (void)in_sizes; (void)n_in; (void)out_size;
    const float* x  = (const float*)d_in[0];
    const float* Wq = (const float*)d_in[2];
    const float* Wk = (const float*)d_in[3];
    const float* Wv = (const float*)d_in[4];
    const float* Wo = (const float*)d_in[5];
    float* out = (float*)d_out;

    __nv_bfloat16 *xhi, *xlo, *yhi, *ylo, *whi, *wlo;
    __nv_bfloat16 *qhi, *qlo, *khi, *klo, *vthi, *vtlo;
    cudaGetSymbolAddress((void**)&xhi, g_xhi);
    cudaGetSymbolAddress((void**)&xlo, g_xlo);
    cudaGetSymbolAddress((void**)&yhi, g_yhi);
    cudaGetSymbolAddress((void**)&ylo, g_ylo);
    cudaGetSymbolAddress((void**)&whi, g_whi);
    cudaGetSymbolAddress((void**)&wlo, g_wlo);
    cudaGetSymbolAddress((void**)&qhi, g_qhi);
    cudaGetSymbolAddress((void**)&qlo, g_qlo);
    cudaGetSymbolAddress((void**)&khi, g_khi);
    cudaGetSymbolAddress((void**)&klo, g_klo);
    cudaGetSymbolAddress((void**)&vthi, g_vthi);
    cudaGetSymbolAddress((void**)&vtlo, g_vtlo);

    void* pfn = nullptr;
    cudaDriverEntryPointQueryResult qres;
    cudaGetDriverEntryPoint("cuTensorMapEncodeTiled", &pfn, cudaEnableDefault, &qres);
    PFN_tmap enc = (PFN_tmap)pfn;

    static CUtensorMap mQh, mQl, mKh, mKl, mVh, mVl;
    mk2d(enc, &mQh, qhi, 64, 128);
    mk2d(enc, &mQl, qlo, 64, 128);
    mk2d(enc, &mKh, khi, 64, 64);
    mk2d(enc, &mKl, klo, 64, 64);
    mk2d(enc, &mVh, vthi, 64, 128);
    mk2d(enc, &mVl, vtlo, 64, 128);

    cudaFuncSetAttribute(gemm_qkv_kernel,
                         cudaFuncAttributeMaxDynamicSharedMemorySize, GSMEM_TOTAL);
    cudaFuncSetAttribute(gemm_out_kernel,
                         cudaFuncAttributeMaxDynamicSharedMemorySize, GSMEM_TOTAL);
    cudaFuncSetAttribute(attn_tc_kernel,
                         cudaFuncAttributeMaxDynamicSharedMemorySize, AT_TOTAL);

    const int n4x = M_ROWS * D_MODEL / 4;
    const int n4w = DD / 4;
    split_bf16_kernel<<<n4x / 256, 256>>>(x, xhi, xlo, n4x);
    wsplit4_kernel<<<dim3(n4w / 256, 4), 256>>>(Wq, Wk, Wv, Wo, whi, wlo, n4w);

    const float qscale = 0.08838834764831845f * LOG2E;
    gemm_qkv_kernel<<<dim3(24, 32), 256, GSMEM_TOTAL>>>(
        xhi, xlo, whi, wlo, qhi, qlo, khi, klo, vthi, vtlo, qscale);

    attn_tc_kernel<<<NSM, 256, AT_TOTAL>>>(mQh, mQl, mKh, mKl, mVh, mVl, yhi, ylo);

    gemm_out_kernel<<<dim3(8, 32), 256, GSMEM_TOTAL>>>(
        yhi, ylo, whi + 3 * (size_t)DD, wlo + 3 * (size_t)DD, out, D_MODEL, D_MODEL);
}

// round 13
// speedup vs baseline: 1.5054x; 1.5054x over previous
#include <cuda_runtime.h>
#include <cuda.h>
#include <cuda_bf16.h>
#include <math.h>
#include <stdint.h>

#if defined(__CUDA_ARCH__)
#if defined(__CUDA_ARCH_FEAT_SM103_ALL) || defined(__CUDA_ARCH_FEAT_SM100_ALL) || defined(__CUDA_ARCH_FEAT_SM101_ALL)
#define TCGEN05_OK 1
#else
#define TCGEN05_OK 0
#endif
#else
#define TCGEN05_OK 0
#endif

#define NBATCH  2
#define S_LEN   2048
#define D_MODEL 2048
#define DHEAD   128
#define M_ROWS  4096
#define DD      (D_MODEL * D_MODEL)
#define NSM     148
#define NITEMS  512
#define LOG2E   1.4426950408889634f

// ---------------- scratch ----------------
__device__ __nv_bfloat16 g_xhi[(size_t)M_ROWS * D_MODEL];
__device__ __nv_bfloat16 g_xlo[(size_t)M_ROWS * D_MODEL];
__device__ __nv_bfloat16 g_yhi[(size_t)M_ROWS * D_MODEL];
__device__ __nv_bfloat16 g_ylo[(size_t)M_ROWS * D_MODEL];
__device__ __nv_bfloat16 g_whi[(size_t)4 * DD];
__device__ __nv_bfloat16 g_wlo[(size_t)4 * DD];
__device__ __nv_bfloat16 g_qhi[(size_t)M_ROWS * D_MODEL];
__device__ __nv_bfloat16 g_qlo[(size_t)M_ROWS * D_MODEL];
__device__ __nv_bfloat16 g_khi[(size_t)M_ROWS * D_MODEL];
__device__ __nv_bfloat16 g_klo[(size_t)M_ROWS * D_MODEL];
__device__ __nv_bfloat16 g_vthi[(size_t)M_ROWS * D_MODEL];  // [b*2048+d][s]
__device__ __nv_bfloat16 g_vtlo[(size_t)M_ROWS * D_MODEL];

// ---------------- PTX helpers ----------------
__device__ __forceinline__ uint32_t smem_u32(const void* p) {
    uint32_t a;
    asm("{ .reg .u64 t; cvta.to.shared.u64 t, %1; cvt.u32.u64 %0, t; }"
        : "=r"(a) : "l"(p));
    return a;
}
__device__ __forceinline__ void mbar_init(uint32_t addr, uint32_t count) {
    asm volatile("mbarrier.init.shared.b64 [%0], %1;" :: "r"(addr), "r"(count) : "memory");
}
__device__ __forceinline__ void mbar_inval(uint32_t addr) {
    asm volatile("mbarrier.inval.shared.b64 [%0];" :: "r"(addr) : "memory");
}
__device__ __forceinline__ void mbar_wait(uint32_t addr, uint32_t parity) {
    asm volatile(
        "{\n\t.reg .pred P;\n\t"
        "WL_%=:\n\t"
        "mbarrier.try_wait.parity.acquire.cta.shared::cta.b64 P, [%0], %1, 0x989680;\n\t"
        "@P bra.uni WD_%=;\n\t"
        "bra.uni WL_%=;\n\t"
        "WD_%=:\n\t}"
        :: "r"(addr), "r"(parity) : "memory");
}
__device__ __forceinline__ void mbar_expect(uint32_t mbar, uint32_t bytes) {
    asm volatile("mbarrier.arrive.expect_tx.shared.b64 _, [%0], %1;"
                 :: "r"(mbar), "r"(bytes) : "memory");
}
__device__ __forceinline__ void tma2d(uint32_t dst, const CUtensorMap* m,
                                      int x, int y, uint32_t mbar) {
    asm volatile(
        "cp.async.bulk.tensor.2d.shared::cta.global.tile.mbarrier::complete_tx::bytes "
        "[%0], [%1, {%2, %3}], [%4];"
        :: "r"(dst), "l"(m), "r"(x), "r"(y), "r"(mbar) : "memory");
}
__device__ __forceinline__ void tmem_alloc(uint32_t smem_dst, uint32_t ncols) {
#if TCGEN05_OK
    asm volatile("tcgen05.alloc.cta_group::1.sync.aligned.shared::cta.b32 [%0], %1;"
                 :: "r"(smem_dst), "r"(ncols) : "memory");
#endif
}
__device__ __forceinline__ void tmem_dealloc(uint32_t tmem, uint32_t ncols) {
#if TCGEN05_OK
    asm volatile("tcgen05.dealloc.cta_group::1.sync.aligned.b32 %0, %1;"
                 :: "r"(tmem), "r"(ncols));
#endif
}
__device__ __forceinline__ void tmem_relinquish() {
#if TCGEN05_OK
    asm volatile("tcgen05.relinquish_alloc_permit.cta_group::1.sync.aligned;");
#endif
}
__device__ __forceinline__ void mma_f16_ss(uint32_t d_tmem, uint64_t a_desc,
                                           uint64_t b_desc, uint32_t idesc,
                                           uint32_t enable_d) {
#if TCGEN05_OK
    asm volatile(
        "{\n\t.reg .pred p;\n\t"
        "setp.ne.u32 p, %4, 0;\n\t"
        "tcgen05.mma.cta_group::1.kind::f16 [%0], %1, %2, %3, {%5, %5, %5, %5}, p;\n\t}"
        :: "r"(d_tmem), "l"(a_desc), "l"(b_desc), "r"(idesc), "r"(enable_d), "r"(0u)
        : "memory");
#endif
}
__device__ __forceinline__ void mma_commit(uint32_t mbar_addr) {
#if TCGEN05_OK
    asm volatile(
        "tcgen05.commit.cta_group::1.mbarrier::arrive::one.shared::cluster.b64 [%0];"
        :: "r"(mbar_addr) : "memory");
#endif
}
__device__ __forceinline__ void tcg_fence_after() {
#if TCGEN05_OK
    asm volatile("tcgen05.fence::after_thread_sync;" ::: "memory");
#endif
}
__device__ __forceinline__ void fence_proxy_async_s() {
    asm volatile("fence.proxy.async.shared::cta;" ::: "memory");
}
__device__ __forceinline__ void tcg_wait_ld() {
#if TCGEN05_OK
    asm volatile("tcgen05.wait::ld.sync.aligned;" ::: "memory");
#endif
}
__device__ __forceinline__ void ldtm_x32(uint32_t* r, uint32_t addr) {
#if TCGEN05_OK
    asm volatile(
        "tcgen05.ld.sync.aligned.32x32b.x32.b32 "
        "{%0, %1, %2, %3, %4, %5, %6, %7, "
        " %8, %9, %10, %11, %12, %13, %14, %15, "
        " %16, %17, %18, %19, %20, %21, %22, %23, "
        " %24, %25, %26, %27, %28, %29, %30, %31}, [%32];"
        : "=r"(r[0]),  "=r"(r[1]),  "=r"(r[2]),  "=r"(r[3]),
          "=r"(r[4]),  "=r"(r[5]),  "=r"(r[6]),  "=r"(r[7]),
          "=r"(r[8]),  "=r"(r[9]),  "=r"(r[10]), "=r"(r[11]),
          "=r"(r[12]), "=r"(r[13]), "=r"(r[14]), "=r"(r[15]),
          "=r"(r[16]), "=r"(r[17]), "=r"(r[18]), "=r"(r[19]),
          "=r"(r[20]), "=r"(r[21]), "=r"(r[22]), "=r"(r[23]),
          "=r"(r[24]), "=r"(r[25]), "=r"(r[26]), "=r"(r[27]),
          "=r"(r[28]), "=r"(r[29]), "=r"(r[30]), "=r"(r[31])
        : "r"(addr));
#else
    for (int i = 0; i < 32; i++) r[i] = 0;
#endif
}

#define DESC_BASE ((2ull << 61) | (1ull << 46) | (64ull << 32) | (1ull << 16))
#define IDESC_N256 ((1u << 4) | (1u << 7) | (1u << 10) | (32u << 17) | (8u << 24))
#define IDESC_N128 ((1u << 4) | (1u << 7) | (1u << 10) | (16u << 17) | (8u << 24))
#define IDESC_N64  ((1u << 4) | (1u << 7) | (1u << 10) | (8u << 17)  | (8u << 24))

__device__ __forceinline__ uint32_t sw128(uint32_t bo) {
    return bo ^ ((bo >> 3) & 0x70);
}
__device__ __forceinline__ uint32_t pack_bf2(float a, float b) {
    __nv_bfloat162 v;
    v.x = __float2bfloat16(a);
    v.y = __float2bfloat16(b);
    return *(uint32_t*)&v;
}
__device__ __forceinline__ float ex2f(float x) {
    float y;
    asm("ex2.approx.ftz.f32 %0, %1;" : "=f"(y) : "f"(x));
    return y;
}

// ---------------- fp32 -> (hi, lo) bf16 split ----------------
__device__ __forceinline__ void split_body(const float* src, __nv_bfloat16* hi,
                                           __nv_bfloat16* lo, int i) {
    float4 v = ((const float4*)src)[i];
    __nv_bfloat16 h0 = __float2bfloat16(v.x);
    __nv_bfloat16 h1 = __float2bfloat16(v.y);
    __nv_bfloat16 h2 = __float2bfloat16(v.z);
    __nv_bfloat16 h3 = __float2bfloat16(v.w);
    uint2 hh, ll;
    hh.x = pack_bf2(v.x, v.y); hh.y = pack_bf2(v.z, v.w);
    ll.x = pack_bf2(v.x - __bfloat162float(h0), v.y - __bfloat162float(h1));
    ll.y = pack_bf2(v.z - __bfloat162float(h2), v.w - __bfloat162float(h3));
    *(uint2*)(hi + 4 * (size_t)i) = hh;
    *(uint2*)(lo + 4 * (size_t)i) = ll;
}

__global__ __launch_bounds__(256) void split_bf16_kernel(
    const float* __restrict__ src,
    __nv_bfloat16* __restrict__ hi, __nv_bfloat16* __restrict__ lo, int n4)
{
    int i = blockIdx.x * 256 + threadIdx.x;
    if (i < n4) split_body(src, hi, lo, i);
}

__global__ __launch_bounds__(256) void wsplit4_kernel(
    const float* __restrict__ s0, const float* __restrict__ s1,
    const float* __restrict__ s2, const float* __restrict__ s3,
    __nv_bfloat16* __restrict__ hi, __nv_bfloat16* __restrict__ lo, int n4)
{
    int i = blockIdx.x * 256 + threadIdx.x;
    if (i >= n4) return;
    int k = blockIdx.y;
    const float* src = (k == 0) ? s0 : (k == 1) ? s1 : (k == 2) ? s2 : s3;
    split_body(src, hi + (size_t)k * DD, lo + (size_t)k * DD, i);
}

// ---------------- TMA-fed 128x256 combined-term GEMM ----------------
// Per chunk (64 K): 4 TMA loads (A hi/lo 16K box 64x128; B hi/lo 32K box 64x256)
#define GST_A_HI 0
#define GST_A_LO 16384
#define GST_B_HI 32768
#define GST_B_LO 65536
#define GST_SIZE 98304
#define G_OFF(s) (1024 + (s) * GST_SIZE)
#define GSMEM_TOTAL (1024 + 2 * GST_SIZE)
// mbars: sb+8 mma0, sb+16 mma1, sb+40 full0, sb+48 full1

#if TCGEN05_OK
__device__ __forceinline__ void gemm_tma_fill(
    uint32_t sb, int buf, const CUtensorMap* mAh, const CUtensorMap* mAl,
    const CUtensorMap* mBh, const CUtensorMap* mBl,
    int k0, int bm, int yB, uint32_t mbar)
{
    mbar_expect(mbar, (uint32_t)GST_SIZE);
    tma2d(sb + G_OFF(buf) + GST_A_HI, mAh, k0, bm, mbar);
    tma2d(sb + G_OFF(buf) + GST_A_LO, mAl, k0, bm, mbar);
    tma2d(sb + G_OFF(buf) + GST_B_HI, mBh, k0, yB, mbar);
    tma2d(sb + G_OFF(buf) + GST_B_LO, mBl, k0, yB, mbar);
}

__device__ __forceinline__ void gemm256_tma_mainloop(
    uint32_t sb, uint32_t tmem, int tid,
    const CUtensorMap* mAh, const CUtensorMap* mAl,
    const CUtensorMap* mBh, const CUtensorMap* mBl,
    int bm, int yB)
{
    if (tid == 0) {
        uint32_t phF0 = 0, phF1 = 0, phM0 = 0, phM1 = 0;
        gemm_tma_fill(sb, 0, mAh, mAl, mBh, mBl, 0, bm, yB, sb + 40);
        for (int i = 0; i < 32; i++) {
            const int buf = i & 1;
            if (i + 1 < 32) {
                const int nb = (i + 1) & 1;
                if (i >= 1) {        // MMA of chunk i-1 (buffer nb) must be done
                    if (nb == 0) { mbar_wait(sb + 8, phM0);  phM0 ^= 1; }
                    else         { mbar_wait(sb + 16, phM1); phM1 ^= 1; }
                }
                gemm_tma_fill(sb, nb, mAh, mAl, mBh, mBl, (i + 1) * 64, bm, yB,
                              sb + 40 + nb * 8);
            }
            if (buf == 0) { mbar_wait(sb + 40, phF0); phF0 ^= 1; }
            else          { mbar_wait(sb + 48, phF1); phF1 ^= 1; }
            const uint32_t off = G_OFF(buf);
            uint64_t dAh = DESC_BASE | ((uint64_t)((sb + off + GST_A_HI) >> 4) & 0x3FFF);
            uint64_t dAl = DESC_BASE | ((uint64_t)((sb + off + GST_A_LO) >> 4) & 0x3FFF);
            uint64_t dBh = DESC_BASE | ((uint64_t)((sb + off + GST_B_HI) >> 4) & 0x3FFF);
            uint64_t dBl = DESC_BASE | ((uint64_t)((sb + off + GST_B_LO) >> 4) & 0x3FFF);
#pragma unroll
            for (int k = 0; k < 4; k++)
                mma_f16_ss(tmem, dAh + k * 2, dBh + k * 2, IDESC_N256, !(i == 0 && k == 0));
#pragma unroll
            for (int k = 0; k < 4; k++)
                mma_f16_ss(tmem, dAh + k * 2, dBl + k * 2, IDESC_N256, 1u);
#pragma unroll
            for (int k = 0; k < 4; k++)
                mma_f16_ss(tmem, dAl + k * 2, dBh + k * 2, IDESC_N256, 1u);
            mma_commit(buf ? (sb + 16) : (sb + 8));
        }
    }
    // chunk31 commit (mma1, 16th commit -> parity 1) implies ALL MMAs done
    mbar_wait(sb + 16, 1);
    tcg_fence_after();
    __syncthreads();
}
#endif

// out-projection: fp32 epilogue
__global__ __launch_bounds__(256) void gemm_out_kernel(
    const __grid_constant__ CUtensorMap mAh, const __grid_constant__ CUtensorMap mAl,
    const __grid_constant__ CUtensorMap mBh, const __grid_constant__ CUtensorMap mBl,
    float* __restrict__ C)
{
#if TCGEN05_OK
    extern __shared__ char smem[];
    const uint32_t sb = smem_u32(smem);
    const int tid = threadIdx.x;
    const int wid = tid >> 5;
    const int lid = tid & 31;
    const int bm = blockIdx.y * 128;
    const int bn = blockIdx.x * 256;
    const int N = D_MODEL;

    if (wid == 0) { tmem_alloc(sb, 256); tmem_relinquish(); }
    if (tid == 0) {
        mbar_init(sb + 8, 1);  mbar_init(sb + 16, 1);
        mbar_init(sb + 40, 1); mbar_init(sb + 48, 1);
    }
    __syncthreads();
    uint32_t tmem;
    asm volatile("ld.shared.b32 %0, [%1];" : "=r"(tmem) : "r"(sb));

    gemm256_tma_mainloop(sb, tmem, tid, &mAh, &mAl, &mBh, &mBl,
                         bm, 3 * 2048 + bn);

    float* st = (float*)(smem + 1024);
#pragma unroll
    for (int hb = 0; hb < 4; hb++) {
        if (wid < 4) {
            uint32_t d0[32], d1[32];
            ldtm_x32(d0, tmem + hb * 64);
            ldtm_x32(d1, tmem + hb * 64 + 32);
            tcg_wait_ld();
            float* srow = st + (wid * 32 + lid) * 68;
#pragma unroll
            for (int c = 0; c < 32; c++) {
                srow[c]      = __uint_as_float(d0[c]);
                srow[32 + c] = __uint_as_float(d1[c]);
            }
        }
        __syncthreads();
#pragma unroll
        for (int j = 0; j < 8; j++) {
            int u = tid + j * 256;
            int row = u >> 4, c4 = u & 15;
            float4 v = *(const float4*)(st + row * 68 + c4 * 4);
            *(float4*)(C + (size_t)(bm + row) * N + bn + hb * 64 + c4 * 4) = v;
        }
        __syncthreads();
    }
    if (tid == 0) {
        mbar_inval(sb + 8);  mbar_inval(sb + 16);
        mbar_inval(sb + 40); mbar_inval(sb + 48);
    }
    if (wid == 0) tmem_dealloc(tmem, 256);
#endif
}

// fused QKV: rgn 0=Q(hi/lo, scaled), 1=K(hi/lo), 2=V -> TRANSPOSED hi/lo
__global__ __launch_bounds__(256) void gemm_qkv_kernel(
    const __grid_constant__ CUtensorMap mAh, const __grid_constant__ CUtensorMap mAl,
    const __grid_constant__ CUtensorMap mBh, const __grid_constant__ CUtensorMap mBl,
    __nv_bfloat16* __restrict__ Qh, __nv_bfloat16* __restrict__ Ql,
    __nv_bfloat16* __restrict__ Kh, __nv_bfloat16* __restrict__ Kl,
    __nv_bfloat16* __restrict__ VTh, __nv_bfloat16* __restrict__ VTl,
    float qscale)
{
#if TCGEN05_OK
    extern __shared__ char smem[];
    const uint32_t sb = smem_u32(smem);
    const int tid = threadIdx.x;
    const int wid = tid >> 5;
    const int lid = tid & 31;
    const int rgn = blockIdx.x >> 3;
    const int bn  = (blockIdx.x & 7) * 256;
    const int bm  = blockIdx.y * 128;
    const int N   = D_MODEL;

    if (wid == 0) { tmem_alloc(sb, 256); tmem_relinquish(); }
    if (tid == 0) {
        mbar_init(sb + 8, 1);  mbar_init(sb + 16, 1);
        mbar_init(sb + 40, 1); mbar_init(sb + 48, 1);
    }
    __syncthreads();
    uint32_t tmem;
    asm volatile("ld.shared.b32 %0, [%1];" : "=r"(tmem) : "r"(sb));

    gemm256_tma_mainloop(sb, tmem, tid, &mAh, &mAl, &mBh, &mBl,
                         bm, rgn * 2048 + bn);

    const float scale = (rgn == 0) ? qscale : 1.0f;
    float* st = (float*)(smem + 1024);
    const int bQ = bm >> 11;
    const int sBase = bm & 2047;
#pragma unroll
    for (int hb = 0; hb < 4; hb++) {
        if (wid < 4) {
            uint32_t d0[32], d1[32];
            ldtm_x32(d0, tmem + hb * 64);
            ldtm_x32(d1, tmem + hb * 64 + 32);
            tcg_wait_ld();
            float* srow = st + (wid * 32 + lid) * 68;
#pragma unroll
            for (int c = 0; c < 32; c++) {
                srow[c]      = __uint_as_float(d0[c]);
                srow[32 + c] = __uint_as_float(d1[c]);
            }
        }
        __syncthreads();
        if (rgn == 2) {
            // transposed V write, pair-vectorized over s (row pairs)
#pragma unroll
            for (int j = 0; j < 16; j++) {
                int u = tid + j * 256;          // 4096 = 64 d-cols x 64 row-pairs
                int rp = (u & 63) * 2, c = u >> 6;
                float v0 = st[rp * 68 + c];
                float v1 = st[(rp + 1) * 68 + c];
                __nv_bfloat16 h0 = __float2bfloat16(v0);
                __nv_bfloat16 h1 = __float2bfloat16(v1);
                uint32_t hp = pack_bf2(v0, v1);
                uint32_t lp = pack_bf2(v0 - __bfloat162float(h0),
                                       v1 - __bfloat162float(h1));
                size_t d = (size_t)(bn + hb * 64 + c);
                size_t addr = ((size_t)bQ * D_MODEL + d) * S_LEN + sBase + rp;
                *(uint32_t*)(VTh + addr) = hp;
                *(uint32_t*)(VTl + addr) = lp;
            }
        } else {
#pragma unroll
            for (int j = 0; j < 8; j++) {
                int u = tid + j * 256;
                int row = u >> 4, c4 = u & 15;
                float4 v = *(const float4*)(st + row * 68 + c4 * 4);
                size_t grow = (size_t)(bm + row);
                int gcol = bn + hb * 64 + c4 * 4;
                float v0 = v.x * scale, v1 = v.y * scale;
                float v2 = v.z * scale, v3 = v.w * scale;
                __nv_bfloat16 h0 = __float2bfloat16(v0);
                __nv_bfloat16 h1 = __float2bfloat16(v1);
                __nv_bfloat16 h2 = __float2bfloat16(v2);
                __nv_bfloat16 h3 = __float2bfloat16(v3);
                uint2 hh, ll;
                hh.x = pack_bf2(v0, v1); hh.y = pack_bf2(v2, v3);
                ll.x = pack_bf2(v0 - __bfloat162float(h0), v1 - __bfloat162float(h1));
                ll.y = pack_bf2(v2 - __bfloat162float(h2), v3 - __bfloat162float(h3));
                __nv_bfloat16* H = (rgn == 0) ? Qh : Kh;
                __nv_bfloat16* L = (rgn == 0) ? Ql : Kl;
                *(uint2*)(H + grow * N + gcol) = hh;
                *(uint2*)(L + grow * N + gcol) = ll;
            }
        }
        __syncthreads();
    }
    if (tid == 0) {
        mbar_inval(sb + 8);  mbar_inval(sb + 16);
        mbar_inval(sb + 40); mbar_inval(sb + 48);
    }
    if (wid == 0) tmem_dealloc(tmem, 256);
#endif
}

// ---------------- persistent attention (R10, unchanged) ----------------
#define AT_RED    1024
#define AT_QHI    3072
#define AT_QLO    35840
#define AT_KV0    68608
#define AT_KV1    134144
#define AT_PHI    199680
#define AT_PLO    216064
#define AT_TOTAL  232448
#define AT_STAGE  AT_KV0

#if TCGEN05_OK
__device__ __forceinline__ void fill_kv_tma(
    uint32_t sb, uint32_t kvb,
    const CUtensorMap* mKh, const CUtensorMap* mKl,
    const CUtensorMap* mVh, const CUtensorMap* mVl,
    int b, int bh, int h, int jt, uint32_t mbar)
{
    const int kx = h * 128, ky = b * S_LEN + jt * 64;
    tma2d(sb + kvb,         mKh, kx,      ky, mbar);
    tma2d(sb + kvb + 8192,  mKh, kx + 64, ky, mbar);
    tma2d(sb + kvb + 16384, mKl, kx,      ky, mbar);
    tma2d(sb + kvb + 24576, mKl, kx + 64, ky, mbar);
    tma2d(sb + kvb + 32768, mVh, jt * 64, bh * 128, mbar);
    tma2d(sb + kvb + 49152, mVl, jt * 64, bh * 128, mbar);
}
__device__ __forceinline__ void issue_qk(uint32_t sb, uint32_t S_T, uint32_t kvb) {
    uint64_t dQh = DESC_BASE | ((uint64_t)((sb + AT_QHI) >> 4) & 0x3FFF);
    uint64_t dQl = DESC_BASE | ((uint64_t)((sb + AT_QLO) >> 4) & 0x3FFF);
    uint64_t dKh = DESC_BASE | ((uint64_t)((sb + kvb) >> 4) & 0x3FFF);
    uint64_t dKl = DESC_BASE | ((uint64_t)((sb + kvb + 16384) >> 4) & 0x3FFF);
    const uint64_t qo[8] = {0, 2, 4, 6, 1024, 1026, 1028, 1030};
    const uint64_t ko[8] = {0, 2, 4, 6, 512, 514, 516, 518};
    uint64_t aT[3] = {dQh, dQh, dQl};
    uint64_t bT[3] = {dKh, dKl, dKh};
#pragma unroll
    for (int t = 0; t < 3; t++)
#pragma unroll
        for (int s = 0; s < 8; s++)
            mma_f16_ss(S_T, aT[t] + qo[s], bT[t] + ko[s], IDESC_N64, !(t == 0 && s == 0));
    mma_commit(sb + 8);
}
__device__ __forceinline__ void issue_pv(uint32_t sb, uint32_t O_T, uint32_t kvb,
                                         int first, int do_commit) {
    uint64_t dPh = DESC_BASE | ((uint64_t)((sb + AT_PHI) >> 4) & 0x3FFF);
    uint64_t dPl = DESC_BASE | ((uint64_t)((sb + AT_PLO) >> 4) & 0x3FFF);
    uint64_t dVh = DESC_BASE | ((uint64_t)((sb + kvb + 32768) >> 4) & 0x3FFF);
    uint64_t dVl = DESC_BASE | ((uint64_t)((sb + kvb + 49152) >> 4) & 0x3FFF);
    uint64_t aT[3] = {dPh, dPh, dPl};
    uint64_t bT[3] = {dVh, dVl, dVh};
#pragma unroll
    for (int t = 0; t < 3; t++)
#pragma unroll
        for (int s = 0; s < 4; s++)
            mma_f16_ss(O_T, aT[t] + 2 * s, bT[t] + 2 * s, IDESC_N128,
                       !(first && t == 0 && s == 0));
    if (do_commit) mma_commit(sb + 16);
}
#endif

__global__ __launch_bounds__(256) void attn_tc_kernel(
    const __grid_constant__ CUtensorMap mQh, const __grid_constant__ CUtensorMap mQl,
    const __grid_constant__ CUtensorMap mKh, const __grid_constant__ CUtensorMap mKl,
    const __grid_constant__ CUtensorMap mVh, const __grid_constant__ CUtensorMap mVl,
    __nv_bfloat16* __restrict__ Yhi, __nv_bfloat16* __restrict__ Ylo)
{
#if TCGEN05_OK
    extern __shared__ char smem[];
    const uint32_t sb = smem_u32(smem);
    const int tid = threadIdx.x;
    const int w   = tid >> 5;
    const int l   = tid & 31;
    const int r   = (w & 3) * 32 + l;
    const int hf  = w >> 2;
    const uint32_t woff = (uint32_t)(w & 3) << 21;

    if (w == 0) { tmem_alloc(sb, 512); tmem_relinquish(); }
    if (tid == 0) {
        mbar_init(sb + 8, 1);
        mbar_init(sb + 16, 1);
        mbar_init(sb + 24, 1);
        mbar_init(sb + 32, 1);
    }
    __syncthreads();
    uint32_t tmem;
    asm volatile("ld.shared.b32 %0, [%1];" : "=r"(tmem) : "r"(sb));
    const uint32_t S_T0 = tmem;
    const uint32_t S_T1 = tmem + 64;
    const uint32_t O_T  = tmem + 128;

    uint32_t phS = 0, phO = 0, phK0 = 0, phK1 = 0;

    for (int rnd = 0; rnd < 4; rnd++) {
        int s = rnd * NSM + ((rnd & 1) ? (NSM - 1 - (int)blockIdx.x) : (int)blockIdx.x);
        if (s >= NITEMS) continue;
        const int qt = 15 - (s >> 5);
        const int bh = s & 31;
        const int b  = bh >> 4;
        const int h  = bh & 15;
        const int njt = 2 * qt + 2;
        const int qg = qt * 128 + r;

        if (tid == 0) {
            mbar_expect(sb + 24, 131072u);
            const int qx = h * 128, qy = b * S_LEN + qt * 128;
            tma2d(sb + AT_QHI,         &mQh, qx,      qy, sb + 24);
            tma2d(sb + AT_QHI + 16384, &mQh, qx + 64, qy, sb + 24);
            tma2d(sb + AT_QLO,         &mQl, qx,      qy, sb + 24);
            tma2d(sb + AT_QLO + 16384, &mQl, qx + 64, qy, sb + 24);
            fill_kv_tma(sb, AT_KV0, &mKh, &mKl, &mVh, &mVl, b, bh, h, 0, sb + 24);
            mbar_wait(sb + 24, phK0); phK0 ^= 1;
            issue_qk(sb, S_T0, AT_KV0);
        }

        float l_run = 0.0f;

        for (int jt = 0; jt < njt; jt++) {
            const uint32_t kvb  = (jt & 1) ? AT_KV1 : AT_KV0;
            const uint32_t kvbn = (jt & 1) ? AT_KV0 : AT_KV1;
            const uint32_t S_cur = (jt & 1) ? S_T1 : S_T0;

            mbar_wait(sb + 8, phS); phS ^= 1;
            tcg_fence_after();

            if (tid == 0 && jt + 1 < njt) {
                uint32_t kf = sb + 24 + 8 * ((jt + 1) & 1);
                mbar_expect(kf, 65536u);
                fill_kv_tma(sb, kvbn, &mKh, &mKl, &mVh, &mVl, b, bh, h, jt + 1, kf);
            }

            uint32_t sr_[32];
            ldtm_x32(sr_, S_cur + hf * 32 + woff);
            tcg_wait_ld();
            const int kgb = jt * 64 + hf * 32;
            float p[32], psum = 0.0f;
#pragma unroll
            for (int i = 0; i < 32; i++) {
                float x = __uint_as_float(sr_[i]);
                p[i] = (kgb + i > qg) ? 0.0f : ex2f(x);
                psum += p[i];
            }
            l_run += psum;

            {
                uint32_t rowbase = (uint32_t)(r >> 3) * 1024u + (uint32_t)(r & 7) * 128u;
#pragma unroll
                for (int i = 0; i < 32; i += 2) {
                    float p0 = p[i], p1 = p[i + 1];
                    __nv_bfloat16 h0 = __float2bfloat16(p0);
                    __nv_bfloat16 h1 = __float2bfloat16(p1);
                    uint32_t hp = pack_bf2(p0, p1);
                    uint32_t lp = pack_bf2(p0 - __bfloat162float(h0),
                                           p1 - __bfloat162float(h1));
                    uint32_t sw = sw128(rowbase + (uint32_t)(hf * 32 + i) * 2u);
                    *(uint32_t*)(smem + AT_PHI + sw) = hp;
                    *(uint32_t*)(smem + AT_PLO + sw) = lp;
                }
            }
            __syncthreads();

            if (tid == 0) {
                fence_proxy_async_s();
                issue_pv(sb, O_T, kvb, jt == 0, jt == njt - 1);
                if (jt + 1 < njt) {
                    uint32_t kf = sb + 24 + 8 * ((jt + 1) & 1);
                    if ((jt + 1) & 1) { mbar_wait(kf, phK1); phK1 ^= 1; }
                    else              { mbar_wait(kf, phK0); phK0 ^= 1; }
                    issue_qk(sb, (jt & 1) ? S_T0 : S_T1, kvbn);
                }
            }
        }

        mbar_wait(sb + 16, phO); phO ^= 1;
        tcg_fence_after();
        float O[64];
        {
            uint32_t o0[32], o1[32];
            ldtm_x32(o0, O_T + hf * 64 + woff);
            ldtm_x32(o1, O_T + hf * 64 + 32 + woff);
            tcg_wait_ld();
#pragma unroll
            for (int j = 0; j < 32; j++) {
                O[j]      = __uint_as_float(o0[j]);
                O[32 + j] = __uint_as_float(o1[j]);
            }
        }

        __syncthreads();
        {
            float* red1 = (float*)(smem + AT_RED);
            red1[hf * 128 + r] = l_run;
        }
        __syncthreads();
        {
            const float* red1 = (const float*)(smem + AT_RED);
            float inv = 1.0f / (red1[r] + red1[128 + r]);
            float* st = (float*)(smem + AT_STAGE);
#pragma unroll
            for (int j = 0; j < 64; j += 4) {
                float4 v = make_float4(O[j] * inv, O[j + 1] * inv,
                                       O[j + 2] * inv, O[j + 3] * inv);
                *(float4*)(st + r * 132 + hf * 64 + j) = v;
            }
        }
        __syncthreads();
        {
            const float* st = (const float*)(smem + AT_STAGE);
#pragma unroll
            for (int j = 0; j < 16; j++) {
                int u = tid + j * 256;
                int row = u >> 5, c4 = u & 31;
                float4 v = *(const float4*)(st + row * 132 + c4 * 4);
                size_t g = ((size_t)(b * S_LEN + qt * 128 + row)) * D_MODEL + h * DHEAD + c4 * 4;
                __nv_bfloat16 h0 = __float2bfloat16(v.x);
                __nv_bfloat16 h1 = __float2bfloat16(v.y);
                __nv_bfloat16 h2 = __float2bfloat16(v.z);
                __nv_bfloat16 h3 = __float2bfloat16(v.w);
                uint2 hh, ll;
                hh.x = pack_bf2(v.x, v.y); hh.y = pack_bf2(v.z, v.w);
                ll.x = pack_bf2(v.x - __bfloat162float(h0), v.y - __bfloat162float(h1));
                ll.y = pack_bf2(v.z - __bfloat162float(h2), v.w - __bfloat162float(h3));
                *(uint2*)(Yhi + g) = hh;
                *(uint2*)(Ylo + g) = ll;
            }
        }
        __syncthreads();
    }

    if (tid == 0) {
        mbar_inval(sb + 8);  mbar_inval(sb + 16);
        mbar_inval(sb + 24); mbar_inval(sb + 32);
    }
    if (w == 0) tmem_dealloc(tmem, 512);
#endif
}

// ---------------- host ----------------
typedef CUresult (CUDAAPI *PFN_tmap)(
    CUtensorMap*, CUtensorMapDataType, cuuint32_t, void*,
    const cuuint64_t*, const cuuint64_t*, const cuuint32_t*, const cuuint32_t*,
    CUtensorMapInterleave, CUtensorMapSwizzle, CUtensorMapL2promotion,
    CUtensorMapFloatOOBfill);

static void mk2d(PFN_tmap enc, CUtensorMap* m, void* ptr, uint64_t rows,
                 uint32_t b0, uint32_t b1)
{
    cuuint64_t dims[2] = {D_MODEL, rows};
    cuuint64_t strides[1] = {D_MODEL * 2};
    cuuint32_t box[2] = {b0, b1};
    cuuint32_t es[2] = {1, 1};
    enc(m, CU_TENSOR_MAP_DATA_TYPE_BFLOAT16, 2, ptr, dims, strides, box, es,
        CU_TENSOR_MAP_INTERLEAVE_NONE, CU_TENSOR_MAP_SWIZZLE_128B,
        CU_TENSOR_MAP_L2_PROMOTION_L2_128B, CU_TENSOR_MAP_FLOAT_OOB_FILL_NONE);
}

extern "C" void kernel_launch(void* const* d_in, const int* in_sizes, int n_in,
                              void* d_out, int out_size)
{
    (void)in_sizes; (void)n_in; (void)out_size;
    const float* x  = (const float*)d_in[0];
    const float* Wq = (const float*)d_in[2];
    const float* Wk = (const float*)d_in[3];
    const float* Wv = (const float*)d_in[4];
    const float* Wo = (const float*)d_in[5];
    float* out = (float*)d_out;

    __nv_bfloat16 *xhi, *xlo, *yhi, *ylo, *whi, *wlo;
    __nv_bfloat16 *qhi, *qlo, *khi, *klo, *vthi, *vtlo;
    cudaGetSymbolAddress((void**)&xhi, g_xhi);
    cudaGetSymbolAddress((void**)&xlo, g_xlo);
    cudaGetSymbolAddress((void**)&yhi, g_yhi);
    cudaGetSymbolAddress((void**)&ylo, g_ylo);
    cudaGetSymbolAddress((void**)&whi, g_whi);
    cudaGetSymbolAddress((void**)&wlo, g_wlo);
    cudaGetSymbolAddress((void**)&qhi, g_qhi);
    cudaGetSymbolAddress((void**)&qlo, g_qlo);
    cudaGetSymbolAddress((void**)&khi, g_khi);
    cudaGetSymbolAddress((void**)&klo, g_klo);
    cudaGetSymbolAddress((void**)&vthi, g_vthi);
    cudaGetSymbolAddress((void**)&vtlo, g_vtlo);

    void* pfn = nullptr;
    cudaDriverEntryPointQueryResult qres;
    cudaGetDriverEntryPoint("cuTensorMapEncodeTiled", &pfn, cudaEnableDefault, &qres);
    PFN_tmap enc = (PFN_tmap)pfn;

    // attention maps
    static CUtensorMap mQh, mQl, mKh, mKl, mVh, mVl;
    mk2d(enc, &mQh, qhi, M_ROWS, 64, 128);
    mk2d(enc, &mQl, qlo, M_ROWS, 64, 128);
    mk2d(enc, &mKh, khi, M_ROWS, 64, 64);
    mk2d(enc, &mKl, klo, M_ROWS, 64, 64);
    mk2d(enc, &mVh, vthi, M_ROWS, 64, 128);
    mk2d(enc, &mVl, vtlo, M_ROWS, 64, 128);

    // GEMM maps: A boxes 64x128, B (weights) boxes 64x256
    static CUtensorMap mXhA, mXlA, mYhA, mYlA, mWhB, mWlB;
    mk2d(enc, &mXhA, xhi, M_ROWS, 64, 128);
    mk2d(enc, &mXlA, xlo, M_ROWS, 64, 128);
    mk2d(enc, &mYhA, yhi, M_ROWS, 64, 128);
    mk2d(enc, &mYlA, ylo, M_ROWS, 64, 128);
    mk2d(enc, &mWhB, whi, 4 * 2048, 64, 256);
    mk2d(enc, &mWlB, wlo, 4 * 2048, 64, 256);

    cudaFuncSetAttribute(gemm_qkv_kernel,
                         cudaFuncAttributeMaxDynamicSharedMemorySize, GSMEM_TOTAL);
    cudaFuncSetAttribute(gemm_out_kernel,
                         cudaFuncAttributeMaxDynamicSharedMemorySize, GSMEM_TOTAL);
    cudaFuncSetAttribute(attn_tc_kernel,
                         cudaFuncAttributeMaxDynamicSharedMemorySize, AT_TOTAL);

    const int n4x = M_ROWS * D_MODEL / 4;
    const int n4w = DD / 4;
    split_bf16_kernel<<<n4x / 256, 256>>>(x, xhi, xlo, n4x);
    wsplit4_kernel<<<dim3(n4w / 256, 4), 256>>>(Wq, Wk, Wv, Wo, whi, wlo, n4w);

    const float qscale = 0.08838834764831845f * LOG2E;
    gemm_qkv_kernel<<<dim3(24, 32), 256, GSMEM_TOTAL>>>(
        mXhA, mXlA, mWhB, mWlB, qhi, qlo, khi, klo, vthi, vtlo, qscale);

    attn_tc_kernel<<<NSM, 256, AT_TOTAL>>>(mQh, mQl, mKh, mKl, mVh, mVl, yhi, ylo);

    gemm_out_kernel<<<dim3(8, 32), 256, GSMEM_TOTAL>>>(
        mYhA, mYlA, mWhB, mWlB, out);
}